// round 10
// baseline (speedup 1.0000x reference)
#include <cuda_runtime.h>
#include <math.h>

// ---------------------------------------------------------------------------
// SimpleRetention (real-output build, packed f32x2 math).
// Re(out[b,n,h]) = sum_m gamma^(n-m)[n>=m] * Re(Q K^T)[b,n,m] * V[b,m,h]
// Re(QK^T)[n,m] = dot(QQ[n], KK[m]) over K=512 with QQ=[Qc|Qs], KK=[Kc|Ks].
// Decay window 128: gamma^128 ~ 1.4e-6 relative truncation (threshold 1e-3).
// Inner loops use fma.rn.f32x2 (FFMA2): 2 fp32 FMAs per issue slot.
// ---------------------------------------------------------------------------

namespace {
constexpr int BATCH = 4;
constexpr int SEQ   = 2048;
constexpr int HD    = 256;
constexpr int K2W   = 2 * HD;             // 512: concat cos|sin
constexpr int WIN   = 128;
constexpr int NROW  = BATCH * SEQ;        // 8192
constexpr int NJ    = WIN / 64 + 1;       // 3
constexpr float LOG2_GAMMA = -0.15200309344504997f;  // log2(0.9)
}

// scratch
__device__ float2 g_rot [SEQ * HD];
__device__ float  g_QQ  [NROW * K2W];
__device__ float  g_KK  [NROW * K2W];
__device__ float  g_Vm  [NROW * HD];
__device__ float  g_attR[NROW * WIN];

// ---- packed f32x2 helpers --------------------------------------------------
#define FMA_F32X2(d, a, b) \
    asm("fma.rn.f32x2 %0, %1, %2, %0;" : "+l"(d) : "l"(a), "l"(b))

__device__ __forceinline__ unsigned long long dup_f32x2(float x)
{
    unsigned long long r;
    asm("mov.b64 %0, {%1, %1};" : "=l"(r) : "f"(x));
    return r;
}

__device__ __forceinline__ float2 unpack_f32x2(unsigned long long p)
{
    float lo, hi;
    asm("mov.b64 {%0, %1}, %2;" : "=f"(lo), "=f"(hi) : "l"(p));
    return make_float2(lo, hi);
}

// ---------------------------------------------------------------------------
// K0: rotation table
// ---------------------------------------------------------------------------
__global__ __launch_bounds__(256) void rot_kernel(const float* __restrict__ theta)
{
    int idx = blockIdx.x * 256 + threadIdx.x;
    int s = idx >> 8;
    int h = idx & (HD - 1);
    float ph = (float)(s + 1) * theta[h];
    float sn, cs;
    sincosf(ph, &sn, &cs);
    g_rot[idx] = make_float2(cs, sn);
}

// ---------------------------------------------------------------------------
// K1: projections + rotation epilogue. z: 0->Q, 1->K, 2->V.
// ---------------------------------------------------------------------------
__global__ __launch_bounds__(256) void proj_kernel(
    const float* __restrict__ X,  const float* __restrict__ Wq,
    const float* __restrict__ Wk, const float* __restrict__ Wv)
{
    __shared__ __align__(16) float As[32][68];   // X tile, [k][row]
    __shared__ __align__(16) float Bs[32][68];   // W tile, [k][col]

    const int z    = blockIdx.z;
    const float* Wm = (z == 0) ? Wq : (z == 1) ? Wk : Wv;
    const int row0 = blockIdx.x * 64;
    const int col0 = blockIdx.y * 64;
    const int tid  = threadIdx.x;
    const int tx   = tid & 15, ty = tid >> 4;
    const int r0   = ty * 4,  c0 = tx * 4;

    unsigned long long acc2[4][2] = {};

    for (int kk = 0; kk < HD; kk += 32) {
        for (int i = tid; i < 64 * 32; i += 256) {
            int r = i >> 5, k = i & 31;
            As[k][r] = X[(row0 + r) * HD + kk + k];
        }
        for (int i = tid; i < 32 * 64; i += 256) {
            int k = i >> 6, c = i & 63;
            Bs[k][c] = Wm[(kk + k) * HD + col0 + c];
        }
        __syncthreads();

        #pragma unroll 8
        for (int k = 0; k < 32; k++) {
            float4 a = *(const float4*)&As[k][r0];
            ulonglong2 bp = *(const ulonglong2*)&Bs[k][c0];
            unsigned long long ad;
            ad = dup_f32x2(a.x); FMA_F32X2(acc2[0][0], ad, bp.x); FMA_F32X2(acc2[0][1], ad, bp.y);
            ad = dup_f32x2(a.y); FMA_F32X2(acc2[1][0], ad, bp.x); FMA_F32X2(acc2[1][1], ad, bp.y);
            ad = dup_f32x2(a.z); FMA_F32X2(acc2[2][0], ad, bp.x); FMA_F32X2(acc2[2][1], ad, bp.y);
            ad = dup_f32x2(a.w); FMA_F32X2(acc2[3][0], ad, bp.x); FMA_F32X2(acc2[3][1], ad, bp.y);
        }
        __syncthreads();
    }

    float acc[4][4];
    #pragma unroll
    for (int i = 0; i < 4; i++) {
        float2 p0 = unpack_f32x2(acc2[i][0]);
        float2 p1 = unpack_f32x2(acc2[i][1]);
        acc[i][0] = p0.x; acc[i][1] = p0.y; acc[i][2] = p1.x; acc[i][3] = p1.y;
    }

    if (z == 2) {
        #pragma unroll
        for (int i = 0; i < 4; i++)
            #pragma unroll
            for (int j = 0; j < 4; j++)
                g_Vm[(row0 + r0 + i) * HD + col0 + c0 + j] = acc[i][j];
    } else {
        float* dst = (z == 0) ? g_QQ : g_KK;
        #pragma unroll
        for (int i = 0; i < 4; i++) {
            int row = row0 + r0 + i;
            int s   = row & (SEQ - 1);
            #pragma unroll
            for (int j = 0; j < 4; j++) {
                int h = col0 + c0 + j;
                float2 rt = g_rot[s * HD + h];
                dst[row * K2W + h]      = acc[i][j] * rt.x;
                dst[row * K2W + HD + h] = acc[i][j] * rt.y;
            }
        }
    }
}

// ---------------------------------------------------------------------------
// K2: real banded attention = QQ . KK^T (K=512), decayed.
// ---------------------------------------------------------------------------
__global__ __launch_bounds__(256) void att_kernel()
{
    __shared__ __align__(16) float As[32][68];
    __shared__ __align__(16) float Bs[32][68];

    const int b  = blockIdx.z;
    const int n0 = blockIdx.x * 64;
    const int m0 = n0 - 64 * (int)blockIdx.y;
    if (m0 < 0) return;

    const int tid = threadIdx.x;
    const int tx  = tid & 15, ty = tid >> 4;
    const int r0  = ty * 4,  c0 = tx * 4;
    const int qbase = (b * SEQ + n0) * K2W;
    const int kbase = (b * SEQ + m0) * K2W;

    unsigned long long acc2[4][2] = {};

    for (int kk = 0; kk < K2W; kk += 32) {
        for (int i = tid; i < 64 * 32; i += 256) {
            int r = i >> 5, k = i & 31;
            As[k][r] = g_QQ[qbase + r * K2W + kk + k];
            Bs[k][r] = g_KK[kbase + r * K2W + kk + k];
        }
        __syncthreads();

        #pragma unroll 8
        for (int k = 0; k < 32; k++) {
            float4 a = *(const float4*)&As[k][r0];
            ulonglong2 bp = *(const ulonglong2*)&Bs[k][c0];
            unsigned long long ad;
            ad = dup_f32x2(a.x); FMA_F32X2(acc2[0][0], ad, bp.x); FMA_F32X2(acc2[0][1], ad, bp.y);
            ad = dup_f32x2(a.y); FMA_F32X2(acc2[1][0], ad, bp.x); FMA_F32X2(acc2[1][1], ad, bp.y);
            ad = dup_f32x2(a.z); FMA_F32X2(acc2[2][0], ad, bp.x); FMA_F32X2(acc2[2][1], ad, bp.y);
            ad = dup_f32x2(a.w); FMA_F32X2(acc2[3][0], ad, bp.x); FMA_F32X2(acc2[3][1], ad, bp.y);
        }
        __syncthreads();
    }

    float acc[4][4];
    #pragma unroll
    for (int i = 0; i < 4; i++) {
        float2 p0 = unpack_f32x2(acc2[i][0]);
        float2 p1 = unpack_f32x2(acc2[i][1]);
        acc[i][0] = p0.x; acc[i][1] = p0.y; acc[i][2] = p1.x; acc[i][3] = p1.y;
    }

    #pragma unroll
    for (int i = 0; i < 4; i++) {
        int n = n0 + r0 + i;
        #pragma unroll
        for (int j = 0; j < 4; j++) {
            int m = m0 + c0 + j;
            int d = n - m;
            if (d >= 0 && d < WIN) {
                float dec = exp2f((float)d * LOG2_GAMMA);
                g_attR[(b * SEQ + n) * WIN + d] = acc[i][j] * dec;
            }
        }
    }
}

// ---------------------------------------------------------------------------
// K3: Re(out)[b,n,h] = sum_m attR[b,n,n-m] * V[b,m,h]
// ---------------------------------------------------------------------------
__global__ __launch_bounds__(256) void out_kernel(float* __restrict__ out,
                                                  long long out_elems)
{
    __shared__ __align__(16) float Ar[64][68];
    __shared__ __align__(16) float Vs[64][68];

    const int b  = blockIdx.z;
    const int n0 = blockIdx.x * 64;
    const int h0 = blockIdx.y * 64;
    const int tid = threadIdx.x;
    const int tx  = tid & 15, ty = tid >> 4;
    const int r0  = ty * 4,  c0 = tx * 4;

    unsigned long long acc2[4][2] = {};

    for (int jt = 0; jt < NJ; jt++) {
        int m0 = n0 - 64 * jt;
        if (m0 < 0) break;

        for (int i = tid; i < 64 * 64; i += 256) {
            int r = i >> 6, c = i & 63;
            Vs[r][c] = g_Vm[(b * SEQ + m0 + r) * HD + h0 + c];
        }
        for (int i = tid; i < 64 * 64; i += 256) {
            int nl = i >> 6, ml = i & 63;
            int d = 64 * jt + nl - ml;
            Ar[nl][ml] = (d >= 0 && d < WIN)
                       ? g_attR[(b * SEQ + n0 + nl) * WIN + d]
                       : 0.0f;
        }
        __syncthreads();

        #pragma unroll 8
        for (int m = 0; m < 64; m++) {
            ulonglong2 vp = *(const ulonglong2*)&Vs[m][c0];
            unsigned long long ad;
            ad = dup_f32x2(Ar[r0 + 0][m]); FMA_F32X2(acc2[0][0], ad, vp.x); FMA_F32X2(acc2[0][1], ad, vp.y);
            ad = dup_f32x2(Ar[r0 + 1][m]); FMA_F32X2(acc2[1][0], ad, vp.x); FMA_F32X2(acc2[1][1], ad, vp.y);
            ad = dup_f32x2(Ar[r0 + 2][m]); FMA_F32X2(acc2[2][0], ad, vp.x); FMA_F32X2(acc2[2][1], ad, vp.y);
            ad = dup_f32x2(Ar[r0 + 3][m]); FMA_F32X2(acc2[3][0], ad, vp.x); FMA_F32X2(acc2[3][1], ad, vp.y);
        }
        __syncthreads();
    }

    #pragma unroll
    for (int i = 0; i < 4; i++) {
        int n = n0 + r0 + i;
        float2 p0 = unpack_f32x2(acc2[i][0]);
        float2 p1 = unpack_f32x2(acc2[i][1]);
        float accv[4] = {p0.x, p0.y, p1.x, p1.y};
        #pragma unroll
        for (int j = 0; j < 4; j++) {
            int h = h0 + c0 + j;
            long long idx = ((long long)b * SEQ + n) * HD + h;
            if (idx < out_elems)
                out[idx] = accv[j];
        }
    }
}

// ---------------------------------------------------------------------------
// launch
// ---------------------------------------------------------------------------
extern "C" void kernel_launch(void* const* d_in, const int* in_sizes, int n_in,
                              void* d_out, int out_size)
{
    constexpr int XN = BATCH * SEQ * HD;
    constexpr int WN = HD * HD;
    constexpr int TN = HD;

    const float* X = nullptr;
    const float* theta = nullptr;
    const float* W[3] = {nullptr, nullptr, nullptr};
    int wn = 0;

    for (int i = 0; i < n_in; i++) {
        int s = in_sizes[i];
        if (s == XN)                X = (const float*)d_in[i];
        else if (s == TN)           theta = (const float*)d_in[i];
        else if (s == WN && wn < 3) W[wn++] = (const float*)d_in[i];
    }
    if (!X || !theta || wn < 3) return;

    float* out = (float*)d_out;

    rot_kernel<<<SEQ * HD / 256, 256>>>(theta);
    proj_kernel<<<dim3(NROW / 64, HD / 64, 3), 256>>>(X, W[0], W[1], W[2]);
    att_kernel<<<dim3(SEQ / 64, NJ, BATCH), 256>>>();
    out_kernel<<<dim3(SEQ / 64, HD / 64, BATCH), 256>>>(out, (long long)out_size);
}